// round 14
// baseline (speedup 1.0000x reference)
#include <cuda_runtime.h>
#include <math.h>

#define NN 50000
#define EE 400000
#define FF 32
#define HALF_E (EE / 2)
#define ET 128   // edges per tile
#define TT 256   // threads per tile block
#define NTILE (EE / ET)

typedef unsigned long long ull;
typedef unsigned int uint;

// ---------------- scratch ----------------
// e-feature buffers TRANSPOSED: [FF][EE]
__device__ __align__(128) float g_e1[(size_t)EE * FF];
__device__ __align__(128) float g_e2[(size_t)EE * FF];
__device__ __align__(128) float g_e3[(size_t)EE * FF];
__device__ __align__(128) float g_acc1[(size_t)NN * FF];
__device__ __align__(128) float g_acc2[(size_t)NN * FF];
__device__ __align__(128) float g_acc3[(size_t)NN * FF];
__device__ __align__(128) float g_uv[(size_t)NN * 64];
__device__ __align__(128) float g_cnt[NN];
__device__ __align__(16) float g_wx[FF * 4];
__device__ __align__(16) float g_bx[4];
__device__ __align__(16) float g_wz[FF];
__device__ float g_bz;

// ---------------- helpers ----------------
__device__ __forceinline__ void ffma2(ull& d, ull a, ull b) {
    asm("fma.rn.f32x2 %0, %1, %2, %0;" : "+l"(d) : "l"(a), "l"(b));
}
__device__ __forceinline__ ull pk2(float v) {
    ull r;
    asm("mov.b64 %0, {%1, %1};" : "=l"(r) : "f"(v));
    return r;
}
union V32 {
    float f[FF];
    ull u[FF / 2];
};
__device__ __forceinline__ void cpsh(float* dst, const float* src, int n, int tid, int nt) {
    for (int i = tid; i < n; i += nt) dst[i] = src[i];
}
__device__ __forceinline__ void ldbias(V32& h, const float* __restrict__ b) {
#pragma unroll
    for (int j = 0; j < FF; j++) h.f[j] = b[j];
}
__device__ __forceinline__ void relu32(V32& h) {
#pragma unroll
    for (int j = 0; j < FF; j++) h.f[j] = fmaxf(h.f[j], 0.f);
}
__device__ __forceinline__ void red4(float* __restrict__ a, float x, float y, float z, float w) {
    asm volatile("red.global.add.v4.f32 [%0], {%1, %2, %3, %4};" ::"l"(a), "f"(x), "f"(y),
                 "f"(z), "f"(w)
                 : "memory");
}
__device__ __forceinline__ void scatter32(float* __restrict__ acc, const V32& o) {
#pragma unroll
    for (int j = 0; j < FF; j += 4) red4(acc + j, o.f[j], o.f[j + 1], o.f[j + 2], o.f[j + 3]);
}
__device__ __forceinline__ void fmarow1(V32& h, ull v, const float* __restrict__ wr) {
#pragma unroll
    for (int j = 0; j < 8; j++) {
        ulonglong2 w = *(const ulonglong2*)(wr + j * 4);
        ffma2(h.u[2 * j + 0], v, w.x);
        ffma2(h.u[2 * j + 1], v, w.y);
    }
}
__device__ __forceinline__ void fmarow2p(V32& h0, V32& h1, ull v0, ull v1,
                                         const float* __restrict__ wr) {
#pragma unroll
    for (int j = 0; j < 8; j++) {
        ulonglong2 w = *(const ulonglong2*)(wr + j * 4);
        ffma2(h0.u[2 * j + 0], v0, w.x);
        ffma2(h0.u[2 * j + 1], v0, w.y);
        ffma2(h1.u[2 * j + 0], v1, w.x);
        ffma2(h1.u[2 * j + 1], v1, w.y);
    }
}
__device__ __forceinline__ void layer2p(V32& o0, V32& o1, const V32& h0, const V32& h1,
                                        const float* __restrict__ sw1,
                                        const float* __restrict__ sb1) {
    ldbias(o0, sb1);
    ldbias(o1, sb1);
#pragma unroll
    for (int k = 0; k < FF; k++) fmarow2p(o0, o1, pk2(h0.f[k]), pk2(h1.f[k]), sw1 + k * FF);
}
__device__ __forceinline__ void store_relu2T(float* __restrict__ gT, int e0, const V32& o0,
                                             const V32& o1) {
    float* p = gT + e0;
#pragma unroll
    for (int j = 0; j < FF; j++) {
        float2 t = make_float2(fmaxf(o0.f[j], 0.f), fmaxf(o1.f[j], 0.f));
        *(float2*)(p + (size_t)j * EE) = t;
    }
}

// tf32 split helpers
__device__ __forceinline__ uint tf32c(float x) {
    uint u;
    asm("cvt.rna.tf32.f32 %0, %1;" : "=r"(u) : "f"(x));
    return u;
}
__device__ __forceinline__ void tf32split(float x, uint& h, uint& l) {
    h = tf32c(x);
    l = tf32c(x - __uint_as_float(h));
}
__device__ __forceinline__ void mma8(float& d0, float& d1, float& d2, float& d3, uint a0,
                                     uint a1, uint a2, uint a3, uint b0, uint b1) {
    asm volatile(
        "mma.sync.aligned.m16n8k8.row.col.f32.tf32.tf32.f32 "
        "{%0,%1,%2,%3}, {%4,%5,%6,%7}, {%8,%9}, {%0,%1,%2,%3};"
        : "+f"(d0), "+f"(d1), "+f"(d2), "+f"(d3)
        : "r"(a0), "r"(a1), "r"(a2), "r"(a3), "r"(b0), "r"(b1));
}

// ---------------- init / head fold ----------------
__global__ void k_init(const float* __restrict__ beta, float* __restrict__ out) {
    int i = blockIdx.x * blockDim.x + threadIdx.x;
    if (i < NN * FF) {
        g_acc1[i] = 0.f;
        g_acc2[i] = 0.f;
        g_acc3[i] = 0.f;
    }
    if (i < NN) g_cnt[i] = 0.f;
    if (i < 3 * NN) out[(size_t)5 * EE + i] = beta[i];
}
__global__ void k_headfold(const float* __restrict__ wl01, const float* __restrict__ bl01,
                           const float* __restrict__ wl02, const float* __restrict__ bl02,
                           const float* __restrict__ wl1, const float* __restrict__ bl1,
                           const float* __restrict__ wl2, const float* __restrict__ bl2) {
    int t = threadIdx.x;
    if (t < 128) {
        int k = t >> 2, j = t & 3;
        float s = 0.f;
#pragma unroll
        for (int m = 0; m < FF; m++) s += wl01[k * FF + m] * wl1[m * 4 + j];
        g_wx[k * 4 + j] = s;
    }
    if (t < 4) {
        float s = bl1[t];
#pragma unroll
        for (int m = 0; m < FF; m++) s += bl01[m] * wl1[m * 4 + t];
        g_bx[t] = s;
    }
    if (t >= 128 && t < 160) {
        int k = t - 128;
        float s = 0.f;
#pragma unroll
        for (int m = 0; m < FF; m++) s += wl02[k * FF + m] * wl2[m];
        g_wz[k] = s;
    }
    if (t == 160) {
        float s = bl2[0];
#pragma unroll
        for (int m = 0; m < FF; m++) s += bl02[m] * wl2[m];
        g_bz = s;
    }
}

// ---------------- node projection (R11 proven form) ----------------
template <int KP>
__global__ __launch_bounds__(256) void k_node(const float* __restrict__ acca,
                                              const float* __restrict__ accb,
                                              const float* __restrict__ W0,
                                              const float* __restrict__ b0) {
    __shared__ __align__(16) float s_w[2 * KP * FF];
    __shared__ __align__(16) float s_b[FF];
    int tid = threadIdx.x;

    int n = blockIdx.x * 128 + (tid & 127);
    float cnt = (n < NN) ? g_cnt[n] : 1.0f;

    cpsh(s_w, W0, 2 * KP * FF, tid, 256);
    cpsh(s_b, b0, FF, tid, 256);
    __syncthreads();

    int isV = tid >> 7;
    if (n >= NN) return;

    float inv = 1.0f / fmaxf(cnt, 1.0f);
    const float* ws = s_w + (isV ? KP * FF : 0);

    V32 acc;
    if (isV) {
#pragma unroll
        for (int j = 0; j < FF; j++) acc.f[j] = 0.f;
    } else {
        ldbias(acc, s_b);
    }

    const float* xpa = acca + (size_t)n * FF;
#pragma unroll
    for (int k4 = 0; k4 < 8; k4++) {
        float4 xv = *(const float4*)(xpa + k4 * 4);
        xv.x = fmaxf(xv.x, 0.f) * inv;
        xv.y = fmaxf(xv.y, 0.f) * inv;
        xv.z = fmaxf(xv.z, 0.f) * inv;
        xv.w = fmaxf(xv.w, 0.f) * inv;
        int k = k4 * 4;
        fmarow1(acc, pk2(xv.x), ws + (k + 0) * FF);
        fmarow1(acc, pk2(xv.y), ws + (k + 1) * FF);
        fmarow1(acc, pk2(xv.z), ws + (k + 2) * FF);
        fmarow1(acc, pk2(xv.w), ws + (k + 3) * FF);
    }
    if (KP == 64) {
        const float* xpb = accb + (size_t)n * FF;
#pragma unroll
        for (int k4 = 0; k4 < 8; k4++) {
            float4 xv = *(const float4*)(xpb + k4 * 4);
            xv.x = fmaxf(xv.x, 0.f) * inv;
            xv.y = fmaxf(xv.y, 0.f) * inv;
            xv.z = fmaxf(xv.z, 0.f) * inv;
            xv.w = fmaxf(xv.w, 0.f) * inv;
            int k = 32 + k4 * 4;
            fmarow1(acc, pk2(xv.x), ws + (k + 0) * FF);
            fmarow1(acc, pk2(xv.y), ws + (k + 1) * FF);
            fmarow1(acc, pk2(xv.z), ws + (k + 2) * FF);
            fmarow1(acc, pk2(xv.w), ws + (k + 3) * FF);
        }
    }

    float* up = g_uv + (size_t)n * 64 + isV * 32;
#pragma unroll
    for (int j = 0; j < FF; j += 4) *(float4*)(up + j) = *(float4*)(acc.f + j);
}

// ---------------- conv1 (R11 proven pair form) ----------------
__global__ __launch_bounds__(128) void k_conv1(const float* __restrict__ ea,
                                               const int* __restrict__ eidx,
                                               const float* __restrict__ w10,
                                               const float* __restrict__ b10,
                                               const float* __restrict__ w11,
                                               const float* __restrict__ b11) {
    __shared__ __align__(16) float s_w0[4 * FF];
    __shared__ __align__(16) float s_b0[FF];
    __shared__ __align__(16) float s_w1[FF * FF];
    __shared__ __align__(16) float s_b1[FF];
    int tid = threadIdx.x, nt = blockDim.x;

    int p = blockIdx.x * nt + tid;
    bool act = p < HALF_E;
    int e0 = 2 * p, e1 = 2 * p + 1;
    float4 a0, a1;
    int r0 = 0, r1 = 0;
    if (act) {
        a0 = *(const float4*)(ea + (size_t)e0 * 4);
        a1 = *(const float4*)(ea + (size_t)e1 * 4);
        r0 = eidx[e0];
        r1 = eidx[e1];
    }

    cpsh(s_w0, w10, 4 * FF, tid, nt);
    cpsh(s_b0, b10, FF, tid, nt);
    cpsh(s_w1, w11, FF * FF, tid, nt);
    cpsh(s_b1, b11, FF, tid, nt);
    __syncthreads();
    if (!act) return;

    V32 h0, h1;
    ldbias(h0, s_b0);
    ldbias(h1, s_b0);
    fmarow2p(h0, h1, pk2(a0.x), pk2(a1.x), s_w0);
    fmarow2p(h0, h1, pk2(a0.y), pk2(a1.y), s_w0 + FF);
    fmarow2p(h0, h1, pk2(a0.z), pk2(a1.z), s_w0 + 2 * FF);
    fmarow2p(h0, h1, pk2(a0.w), pk2(a1.w), s_w0 + 3 * FF);
    relu32(h0);
    relu32(h1);

    V32 o0, o1;
    layer2p(o0, o1, h0, h1, s_w1, s_b1);

    scatter32(g_acc1 + (size_t)r0 * FF, o0);
    scatter32(g_acc1 + (size_t)r1 * FF, o1);
    atomicAdd(&g_cnt[r0], 1.0f);
    atomicAdd(&g_cnt[r1], 1.0f);
    store_relu2T(g_e1, e0, o0, o1);
}

// ================= tensor-core tile edge kernel =================
// 128-edge tile, 256 threads (8 warps). GEMM via m16n8k8 tf32, 3xTF32 split.
// MODE 0: edge2 (X rows: 0-3 ea, 4-35 e1, 36-39 zero; K1P=40, K1SRC=36)
// MODE 1: edge3 (X rows: 0-31 srcA=e2, 32-63 srcB=e1; K1P=64)
// MODE 2: edge4 (X rows: 0-31 srcA=e3, 32-63 srcB=e2) + folded heads

template <int K1P, int MODE>
__global__ __launch_bounds__(TT) void k_edget(
    const int* __restrict__ eidx, const float* __restrict__ ea,
    const float* __restrict__ srcA, const float* __restrict__ srcB,
    const float* __restrict__ Wsrc, const float* __restrict__ W1src,
    const float* __restrict__ b1src, float* __restrict__ accout,
    float* __restrict__ eout, float* __restrict__ out) {
    extern __shared__ float sm[];
    // smem layout (floats)
    const int XS = 0;
    const int HS = XS + K1P * 132;
    const int WHI = HS + 32 * 132;
    const int WLO = WHI + K1P * 33;
    const int W1HI = WLO + K1P * 33;
    const int W1LO = W1HI + 32 * 33;
    const int UVB = W1LO + 32 * 33;
    const int B1 = UVB + 128 * 33;
    const int IDXR = B1 + 32;
    const int IDXC = IDXR + 128;
    const int HWX = IDXC + 128;
    const int HWZ = HWX + 128;
    const int HBX = HWZ + 32;
    const int HBZ = HBX + 4;

    float* Xs = sm + XS;
    float* Hs = sm + HS;
    float* Whi = sm + WHI;
    float* Wlo = sm + WLO;
    float* W1hi = sm + W1HI;
    float* W1lo = sm + W1LO;
    float* uvb = sm + UVB;
    float* b1s = sm + B1;
    int* ridx = (int*)(sm + IDXR);
    int* cidx = (int*)(sm + IDXC);
    float* Os = sm + XS;  // reuse X region after GEMM1

    int tid = threadIdx.x;
    int base = blockIdx.x * ET;

    // ---- stage X ----
    if (MODE == 0) {
        for (int i = tid; i < 32 * 32; i += TT) {  // e1 rows -> X rows 4..35
            int k = i >> 5, ch = i & 31;
            float4 v = *(const float4*)(srcA + (size_t)k * EE + base + ch * 4);
            *(float4*)(Xs + (k + 4) * 132 + ch * 4) = v;
        }
        if (tid < ET) {  // ea rows 0..3
            float4 a = *(const float4*)(ea + (size_t)(base + tid) * 4);
            Xs[0 * 132 + tid] = a.x;
            Xs[1 * 132 + tid] = a.y;
            Xs[2 * 132 + tid] = a.z;
            Xs[3 * 132 + tid] = a.w;
        }
        for (int i = tid; i < 4 * 132; i += TT) Xs[36 * 132 + i] = 0.f;  // pad rows
    } else {
        for (int i = tid; i < 64 * 32; i += TT) {
            int k = i >> 5, ch = i & 31;
            const float* s = (k < 32) ? srcA + (size_t)k * EE : srcB + (size_t)(k - 32) * EE;
            float4 v = *(const float4*)(s + base + ch * 4);
            *(float4*)(Xs + k * 132 + ch * 4) = v;
        }
    }
    // ---- stage weights (hi/lo) ----
    const int K1SRC = (MODE == 0) ? 36 : 64;
    for (int i = tid; i < K1P * 32; i += TT) {
        int k = i >> 5, n = i & 31;
        float w = (k < K1SRC) ? Wsrc[k * 32 + n] : 0.f;
        uint h, l;
        tf32split(w, h, l);
        Whi[k * 33 + n] = __uint_as_float(h);
        Wlo[k * 33 + n] = __uint_as_float(l);
    }
    for (int i = tid; i < 1024; i += TT) {
        int k = i >> 5, n = i & 31;
        float w = W1src[i];
        uint h, l;
        tf32split(w, h, l);
        W1hi[k * 33 + n] = __uint_as_float(h);
        W1lo[k * 33 + n] = __uint_as_float(l);
    }
    if (tid < 32) b1s[tid] = b1src[tid];
    if (MODE == 2) {
        for (int i = tid; i < 128; i += TT) sm[HWX + i] = g_wx[i];
        if (tid < 32) sm[HWZ + tid] = g_wz[tid];
        if (tid < 4) sm[HBX + tid] = g_bx[tid];
        if (tid == 0) sm[HBZ] = g_bz;
    }
    // ---- stage idx + UV (accumulates bias via U) ----
    if (tid < ET) {
        int e = tid;
        int r = eidx[base + e], c = eidx[EE + base + e];
        ridx[e] = r;
        cidx[e] = c;
        const float4* U = (const float4*)(g_uv + (size_t)r * 64);
        const float4* V = (const float4*)(g_uv + (size_t)c * 64 + 32);
        float* d = uvb + e * 33;
#pragma unroll
        for (int j = 0; j < 8; j++) {
            float4 u = U[j], v = V[j];
            d[4 * j + 0] = u.x + v.x;
            d[4 * j + 1] = u.y + v.y;
            d[4 * j + 2] = u.z + v.z;
            d[4 * j + 3] = u.w + v.w;
        }
    }
    __syncthreads();

    int warp = tid >> 5, lane = tid & 31;
    int g = lane >> 2, tg = lane & 3;
    int m0 = warp * 16;

    // ================ GEMM1: H = relu(UV + X @ W) ================
    {
        float acc[4][4];
#pragma unroll
        for (int nb = 0; nb < 4; nb++) {
            int n0 = nb * 8;
            acc[nb][0] = uvb[(m0 + g) * 33 + n0 + 2 * tg];
            acc[nb][1] = uvb[(m0 + g) * 33 + n0 + 2 * tg + 1];
            acc[nb][2] = uvb[(m0 + g + 8) * 33 + n0 + 2 * tg];
            acc[nb][3] = uvb[(m0 + g + 8) * 33 + n0 + 2 * tg + 1];
        }
#pragma unroll
        for (int k0 = 0; k0 < K1P; k0 += 8) {
            float x0 = Xs[(k0 + tg) * 132 + m0 + g];
            float x1 = Xs[(k0 + tg) * 132 + m0 + g + 8];
            float x2 = Xs[(k0 + tg + 4) * 132 + m0 + g];
            float x3 = Xs[(k0 + tg + 4) * 132 + m0 + g + 8];
            uint a0h, a0l, a1h, a1l, a2h, a2l, a3h, a3l;
            tf32split(x0, a0h, a0l);
            tf32split(x1, a1h, a1l);
            tf32split(x2, a2h, a2l);
            tf32split(x3, a3h, a3l);
#pragma unroll
            for (int nb = 0; nb < 4; nb++) {
                int n0 = nb * 8;
                uint b0h = __float_as_uint(Whi[(k0 + tg) * 33 + n0 + g]);
                uint b1h = __float_as_uint(Whi[(k0 + tg + 4) * 33 + n0 + g]);
                uint b0l = __float_as_uint(Wlo[(k0 + tg) * 33 + n0 + g]);
                uint b1l = __float_as_uint(Wlo[(k0 + tg + 4) * 33 + n0 + g]);
                mma8(acc[nb][0], acc[nb][1], acc[nb][2], acc[nb][3], a0h, a1h, a2h, a3h,
                     b0h, b1h);
                mma8(acc[nb][0], acc[nb][1], acc[nb][2], acc[nb][3], a0h, a1h, a2h, a3h,
                     b0l, b1l);
                mma8(acc[nb][0], acc[nb][1], acc[nb][2], acc[nb][3], a0l, a1l, a2l, a3l,
                     b0h, b1h);
            }
        }
#pragma unroll
        for (int nb = 0; nb < 4; nb++) {
            int n0 = nb * 8;
            Hs[(n0 + 2 * tg) * 132 + m0 + g] = fmaxf(acc[nb][0], 0.f);
            Hs[(n0 + 2 * tg + 1) * 132 + m0 + g] = fmaxf(acc[nb][1], 0.f);
            Hs[(n0 + 2 * tg) * 132 + m0 + g + 8] = fmaxf(acc[nb][2], 0.f);
            Hs[(n0 + 2 * tg + 1) * 132 + m0 + g + 8] = fmaxf(acc[nb][3], 0.f);
        }
    }
    __syncthreads();

    // ================ GEMM2: O = b1 + H @ W1 ================
    {
        float acc[4][4];
#pragma unroll
        for (int nb = 0; nb < 4; nb++) {
            int n0 = nb * 8;
            float bA = b1s[n0 + 2 * tg], bB = b1s[n0 + 2 * tg + 1];
            acc[nb][0] = bA;
            acc[nb][1] = bB;
            acc[nb][2] = bA;
            acc[nb][3] = bB;
        }
#pragma unroll
        for (int k0 = 0; k0 < 32; k0 += 8) {
            float x0 = Hs[(k0 + tg) * 132 + m0 + g];
            float x1 = Hs[(k0 + tg) * 132 + m0 + g + 8];
            float x2 = Hs[(k0 + tg + 4) * 132 + m0 + g];
            float x3 = Hs[(k0 + tg + 4) * 132 + m0 + g + 8];
            uint a0h, a0l, a1h, a1l, a2h, a2l, a3h, a3l;
            tf32split(x0, a0h, a0l);
            tf32split(x1, a1h, a1l);
            tf32split(x2, a2h, a2l);
            tf32split(x3, a3h, a3l);
#pragma unroll
            for (int nb = 0; nb < 4; nb++) {
                int n0 = nb * 8;
                uint b0h = __float_as_uint(W1hi[(k0 + tg) * 33 + n0 + g]);
                uint b1h = __float_as_uint(W1hi[(k0 + tg + 4) * 33 + n0 + g]);
                uint b0l = __float_as_uint(W1lo[(k0 + tg) * 33 + n0 + g]);
                uint b1l = __float_as_uint(W1lo[(k0 + tg + 4) * 33 + n0 + g]);
                mma8(acc[nb][0], acc[nb][1], acc[nb][2], acc[nb][3], a0h, a1h, a2h, a3h,
                     b0h, b1h);
                mma8(acc[nb][0], acc[nb][1], acc[nb][2], acc[nb][3], a0h, a1h, a2h, a3h,
                     b0l, b1l);
                mma8(acc[nb][0], acc[nb][1], acc[nb][2], acc[nb][3], a0l, a1l, a2l, a3l,
                     b0h, b1h);
            }
        }
        __syncthreads();  // X region free (GEMM1 done for all warps)
#pragma unroll
        for (int nb = 0; nb < 4; nb++) {
            int n0 = nb * 8;
            Os[(n0 + 2 * tg) * 132 + m0 + g] = acc[nb][0];
            Os[(n0 + 2 * tg + 1) * 132 + m0 + g] = acc[nb][1];
            Os[(n0 + 2 * tg) * 132 + m0 + g + 8] = acc[nb][2];
            Os[(n0 + 2 * tg + 1) * 132 + m0 + g + 8] = acc[nb][3];
        }
    }
    __syncthreads();

    // ================ finalize ================
    if (MODE != 2) {
        // store relu(o) to transposed e-buffer (coalesced)
        for (int i = tid; i < 32 * ET; i += TT) {
            int n = i >> 7, e = i & 127;
            eout[(size_t)n * EE + base + e] = fmaxf(Os[n * 132 + e], 0.f);
        }
        // scatter pre-relu o to node accumulator (2 threads per edge)
        {
            int e = tid & 127, half = tid >> 7;
            int r = ridx[e];
            float* ap = accout + (size_t)r * FF + half * 16;
#pragma unroll
            for (int j = 0; j < 4; j++) {
                int n = half * 16 + j * 4;
                red4(ap + j * 4, Os[(n + 0) * 132 + e], Os[(n + 1) * 132 + e],
                     Os[(n + 2) * 132 + e], Os[(n + 3) * 132 + e]);
            }
        }
    } else {
        // folded heads per edge
        if (tid < ET) {
            int e = tid;
            int edge = base + e;
            float4 a = *(const float4*)(ea + (size_t)edge * 4);
            float x0 = sm[HBX + 0] + a.x, x1 = sm[HBX + 1] + a.y;
            float x2 = sm[HBX + 2] + a.z, x3 = sm[HBX + 3] + a.w;
            float z = sm[HBZ];
#pragma unroll
            for (int k = 0; k < FF; k++) {
                float v = fmaxf(Os[k * 132 + e], 0.f);  // relu(e4)
                float4 w = *(const float4*)(sm + HWX + k * 4);
                x0 += v * w.x;
                x1 += v * w.y;
                x2 += v * w.z;
                x3 += v * w.w;
                z += v * sm[HWZ + k];
            }
            float nrm = sqrtf(x0 * x0 + x1 * x1 + x2 * x2 + x3 * x3);
            float inv = 1.0f / fmaxf(nrm, 1e-12f);
            *(float4*)(out + (size_t)EE + (size_t)edge * 4) =
                make_float4(x0 * inv, x1 * inv, x2 * inv, x3 * inv);
            out[edge] = 1.0f / (1.0f + expf(-z));
        }
    }
}

// smem totals (floats)
#define ETOT(K1P) ((K1P)*132 + 32 * 132 + 2 * (K1P)*33 + 2 * 32 * 33 + 128 * 33 + 32 + 256 + 165)

// ---------------- launch ----------------
extern "C" void kernel_launch(void* const* d_in, const int* in_sizes, int n_in,
                              void* d_out, int out_size) {
    const int* eidx = (const int*)d_in[1];
    const float* ea = (const float*)d_in[2];
    const float* beta = (const float*)d_in[3];
    const float* w10 = (const float*)d_in[4];
    const float* b10 = (const float*)d_in[5];
    const float* w11 = (const float*)d_in[6];
    const float* b11 = (const float*)d_in[7];
    const float* w20 = (const float*)d_in[8];
    const float* b20 = (const float*)d_in[9];
    const float* w21 = (const float*)d_in[10];
    const float* b21 = (const float*)d_in[11];
    const float* w30 = (const float*)d_in[12];
    const float* b30 = (const float*)d_in[13];
    const float* w31 = (const float*)d_in[14];
    const float* b31 = (const float*)d_in[15];
    const float* w40 = (const float*)d_in[16];
    const float* b40 = (const float*)d_in[17];
    const float* w41 = (const float*)d_in[18];
    const float* b41 = (const float*)d_in[19];
    const float* wl01 = (const float*)d_in[20];
    const float* bl01 = (const float*)d_in[21];
    const float* wl02 = (const float*)d_in[22];
    const float* bl02 = (const float*)d_in[23];
    const float* wl1 = (const float*)d_in[24];
    const float* bl1 = (const float*)d_in[25];
    const float* wl2 = (const float*)d_in[26];
    const float* bl2 = (const float*)d_in[27];
    float* out = (float*)d_out;

    float *acc1p, *acc2p, *acc3p, *e1p, *e2p, *e3p;
    cudaGetSymbolAddress((void**)&acc1p, g_acc1);
    cudaGetSymbolAddress((void**)&acc2p, g_acc2);
    cudaGetSymbolAddress((void**)&acc3p, g_acc3);
    cudaGetSymbolAddress((void**)&e1p, g_e1);
    cudaGetSymbolAddress((void**)&e2p, g_e2);
    cudaGetSymbolAddress((void**)&e3p, g_e3);

    static int attr_done = 0;
    if (!attr_done) {
        cudaFuncSetAttribute(k_edget<40, 0>, cudaFuncAttributeMaxDynamicSharedMemorySize,
                             ETOT(40) * 4);
        cudaFuncSetAttribute(k_edget<64, 1>, cudaFuncAttributeMaxDynamicSharedMemorySize,
                             ETOT(64) * 4);
        cudaFuncSetAttribute(k_edget<64, 2>, cudaFuncAttributeMaxDynamicSharedMemorySize,
                             ETOT(64) * 4);
        attr_done = 1;
    }

    const int T = 256;
    const int gridNF = (NN * FF + T - 1) / T;
    const int TB = 128;
    const int gridP = (HALF_E + TB - 1) / TB;
    const int gridN = (NN + 127) / 128;

    k_init<<<gridNF, T>>>(beta, out);
    k_headfold<<<1, 192>>>(wl01, bl01, wl02, bl02, wl1, bl1, wl2, bl2);
    k_conv1<<<gridP, TB>>>(ea, eidx, w10, b10, w11, b11);

    k_node<32><<<gridN, 256>>>(acc1p, nullptr, w20, b20);
    k_edget<40, 0><<<NTILE, TT, ETOT(40) * 4>>>(eidx, ea, e1p, nullptr, w20 + 64 * FF, w21,
                                                b21, acc2p, e2p, out);

    k_node<64><<<gridN, 256>>>(acc2p, acc1p, w30, b30);
    k_edget<64, 1><<<NTILE, TT, ETOT(64) * 4>>>(eidx, ea, e2p, e1p, w30 + 128 * FF, w31,
                                                b31, acc3p, e3p, out);

    k_node<64><<<gridN, 256>>>(acc3p, acc2p, w40, b40);
    k_edget<64, 2><<<NTILE, TT, ETOT(64) * 4>>>(eidx, ea, e3p, e2p, w40 + 128 * FF, w41,
                                                b41, nullptr, nullptr, out);
}

// round 15
// speedup vs baseline: 1.3258x; 1.3258x over previous
#include <cuda_runtime.h>
#include <math.h>

#define NN 50000
#define EE 400000
#define FF 32
#define HALF_E (EE / 2)
#define ET 128
#define TT 256
#define NTILE (EE / ET)

typedef unsigned long long ull;
typedef unsigned int uint;

// ---------------- scratch ----------------
__device__ __align__(128) float g_e1[(size_t)EE * FF];
__device__ __align__(128) float g_e2[(size_t)EE * FF];
__device__ __align__(128) float g_e3[(size_t)EE * FF];
__device__ __align__(128) float g_acc1[(size_t)NN * FF];
__device__ __align__(128) float g_acc2[(size_t)NN * FF];
__device__ __align__(128) float g_acc3[(size_t)NN * FF];
__device__ __align__(128) float g_uv[(size_t)NN * 64];
__device__ __align__(128) float g_cnt[NN];
__device__ __align__(16) float g_wx[FF * 4];
__device__ __align__(16) float g_bx[4];
__device__ __align__(16) float g_wz[FF];
__device__ float g_bz;
// fragment-ordered split weights: entry = float4(b0h, b1h, b0l, b1l)
__device__ __align__(128) float g_wf20[5 * 128 * 4];
__device__ __align__(128) float g_wf30[8 * 128 * 4];
__device__ __align__(128) float g_wf40[8 * 128 * 4];
__device__ __align__(128) float g_wf21[4 * 128 * 4];
__device__ __align__(128) float g_wf31[4 * 128 * 4];
__device__ __align__(128) float g_wf41[4 * 128 * 4];

// ---------------- f32x2 / misc helpers ----------------
__device__ __forceinline__ void ffma2(ull& d, ull a, ull b) {
    asm("fma.rn.f32x2 %0, %1, %2, %0;" : "+l"(d) : "l"(a), "l"(b));
}
__device__ __forceinline__ ull pk2(float v) {
    ull r;
    asm("mov.b64 %0, {%1, %1};" : "=l"(r) : "f"(v));
    return r;
}
union V32 {
    float f[FF];
    ull u[FF / 2];
};
__device__ __forceinline__ void cpsh(float* dst, const float* src, int n, int tid, int nt) {
    for (int i = tid; i < n; i += nt) dst[i] = src[i];
}
__device__ __forceinline__ void ldbias(V32& h, const float* __restrict__ b) {
#pragma unroll
    for (int j = 0; j < FF; j++) h.f[j] = b[j];
}
__device__ __forceinline__ void relu32(V32& h) {
#pragma unroll
    for (int j = 0; j < FF; j++) h.f[j] = fmaxf(h.f[j], 0.f);
}
__device__ __forceinline__ void red4(float* __restrict__ a, float x, float y, float z, float w) {
    asm volatile("red.global.add.v4.f32 [%0], {%1, %2, %3, %4};" ::"l"(a), "f"(x), "f"(y),
                 "f"(z), "f"(w)
                 : "memory");
}
__device__ __forceinline__ void scatter32(float* __restrict__ acc, const V32& o) {
#pragma unroll
    for (int j = 0; j < FF; j += 4) red4(acc + j, o.f[j], o.f[j + 1], o.f[j + 2], o.f[j + 3]);
}
__device__ __forceinline__ void fmarow1(V32& h, ull v, const float* __restrict__ wr) {
#pragma unroll
    for (int j = 0; j < 8; j++) {
        ulonglong2 w = *(const ulonglong2*)(wr + j * 4);
        ffma2(h.u[2 * j + 0], v, w.x);
        ffma2(h.u[2 * j + 1], v, w.y);
    }
}
__device__ __forceinline__ void fmarow2p(V32& h0, V32& h1, ull v0, ull v1,
                                         const float* __restrict__ wr) {
#pragma unroll
    for (int j = 0; j < 8; j++) {
        ulonglong2 w = *(const ulonglong2*)(wr + j * 4);
        ffma2(h0.u[2 * j + 0], v0, w.x);
        ffma2(h0.u[2 * j + 1], v0, w.y);
        ffma2(h1.u[2 * j + 0], v1, w.x);
        ffma2(h1.u[2 * j + 1], v1, w.y);
    }
}
__device__ __forceinline__ void layer2p(V32& o0, V32& o1, const V32& h0, const V32& h1,
                                        const float* __restrict__ sw1,
                                        const float* __restrict__ sb1) {
    ldbias(o0, sb1);
    ldbias(o1, sb1);
#pragma unroll
    for (int k = 0; k < FF; k++) fmarow2p(o0, o1, pk2(h0.f[k]), pk2(h1.f[k]), sw1 + k * FF);
}
__device__ __forceinline__ void store_relu2T(float* __restrict__ gT, int e0, const V32& o0,
                                             const V32& o1) {
    float* p = gT + e0;
#pragma unroll
    for (int j = 0; j < FF; j++) {
        float2 t = make_float2(fmaxf(o0.f[j], 0.f), fmaxf(o1.f[j], 0.f));
        *(float2*)(p + (size_t)j * EE) = t;
    }
}

// tf32 helpers
__device__ __forceinline__ uint tf32c(float x) {
    uint u;
    asm("cvt.rna.tf32.f32 %0, %1;" : "=r"(u) : "f"(x));
    return u;
}
__device__ __forceinline__ void tf32split(float x, uint& h, uint& l) {
    h = tf32c(x);
    l = tf32c(x - __uint_as_float(h));
}
__device__ __forceinline__ void mma8(float& d0, float& d1, float& d2, float& d3, uint a0,
                                     uint a1, uint a2, uint a3, uint b0, uint b1) {
    asm volatile(
        "mma.sync.aligned.m16n8k8.row.col.f32.tf32.tf32.f32 "
        "{%0,%1,%2,%3}, {%4,%5,%6,%7}, {%8,%9}, {%0,%1,%2,%3};"
        : "+f"(d0), "+f"(d1), "+f"(d2), "+f"(d3)
        : "r"(a0), "r"(a1), "r"(a2), "r"(a3), "r"(b0), "r"(b1));
}

// ---------------- init / head fold / weight pack ----------------
__global__ void k_init(const float* __restrict__ beta, float* __restrict__ out) {
    int i = blockIdx.x * blockDim.x + threadIdx.x;
    if (i < NN * FF) {
        g_acc1[i] = 0.f;
        g_acc2[i] = 0.f;
        g_acc3[i] = 0.f;
    }
    if (i < NN) g_cnt[i] = 0.f;
    if (i < 3 * NN) out[(size_t)5 * EE + i] = beta[i];
}
__global__ void k_headfold(const float* __restrict__ wl01, const float* __restrict__ bl01,
                           const float* __restrict__ wl02, const float* __restrict__ bl02,
                           const float* __restrict__ wl1, const float* __restrict__ bl1,
                           const float* __restrict__ wl2, const float* __restrict__ bl2) {
    int t = threadIdx.x;
    if (t < 128) {
        int k = t >> 2, j = t & 3;
        float s = 0.f;
#pragma unroll
        for (int m = 0; m < FF; m++) s += wl01[k * FF + m] * wl1[m * 4 + j];
        g_wx[k * 4 + j] = s;
    }
    if (t < 4) {
        float s = bl1[t];
#pragma unroll
        for (int m = 0; m < FF; m++) s += bl01[m] * wl1[m * 4 + t];
        g_bx[t] = s;
    }
    if (t >= 128 && t < 160) {
        int k = t - 128;
        float s = 0.f;
#pragma unroll
        for (int m = 0; m < FF; m++) s += wl02[k * FF + m] * wl2[m];
        g_wz[k] = s;
    }
    if (t == 160) {
        float s = bl2[0];
#pragma unroll
        for (int m = 0; m < FF; m++) s += bl02[m] * wl2[m];
        g_bz = s;
    }
}

__device__ __forceinline__ void packfrag(float* dst, const float* W, int nfrag, int ksrc,
                                         int idx) {
    if (idx >= nfrag) return;
    int kb = idx >> 7;
    int rem = idx & 127;
    int nb = rem >> 5, lane = rem & 31;
    int g = lane >> 2, tg = lane & 3;
    int k0 = kb * 8, n = nb * 8 + g;
    float w0 = (k0 + tg < ksrc) ? W[(k0 + tg) * 32 + n] : 0.f;
    float w1 = (k0 + tg + 4 < ksrc) ? W[(k0 + tg + 4) * 32 + n] : 0.f;
    uint h0, l0, h1, l1;
    tf32split(w0, h0, l0);
    tf32split(w1, h1, l1);
    *(float4*)(dst + idx * 4) =
        make_float4(__uint_as_float(h0), __uint_as_float(h1), __uint_as_float(l0),
                    __uint_as_float(l1));
}
__global__ void k_wpack(const float* __restrict__ w20, const float* __restrict__ w21,
                        const float* __restrict__ w30, const float* __restrict__ w31,
                        const float* __restrict__ w40, const float* __restrict__ w41) {
    int idx = blockIdx.x * blockDim.x + threadIdx.x;
    packfrag(g_wf20, w20 + 64 * FF, 5 * 128, 36, idx);
    packfrag(g_wf30, w30 + 128 * FF, 8 * 128, 64, idx);
    packfrag(g_wf40, w40 + 128 * FF, 8 * 128, 64, idx);
    packfrag(g_wf21, w21, 4 * 128, 32, idx);
    packfrag(g_wf31, w31, 4 * 128, 32, idx);
    packfrag(g_wf41, w41, 4 * 128, 32, idx);
}

// ---------------- node projection (R11 proven) ----------------
template <int KP>
__global__ __launch_bounds__(256) void k_node(const float* __restrict__ acca,
                                              const float* __restrict__ accb,
                                              const float* __restrict__ W0,
                                              const float* __restrict__ b0) {
    __shared__ __align__(16) float s_w[2 * KP * FF];
    __shared__ __align__(16) float s_b[FF];
    int tid = threadIdx.x;
    int n = blockIdx.x * 128 + (tid & 127);
    float cnt = (n < NN) ? g_cnt[n] : 1.0f;
    cpsh(s_w, W0, 2 * KP * FF, tid, 256);
    cpsh(s_b, b0, FF, tid, 256);
    __syncthreads();
    int isV = tid >> 7;
    if (n >= NN) return;
    float inv = 1.0f / fmaxf(cnt, 1.0f);
    const float* ws = s_w + (isV ? KP * FF : 0);
    V32 acc;
    if (isV) {
#pragma unroll
        for (int j = 0; j < FF; j++) acc.f[j] = 0.f;
    } else {
        ldbias(acc, s_b);
    }
    const float* xpa = acca + (size_t)n * FF;
#pragma unroll
    for (int k4 = 0; k4 < 8; k4++) {
        float4 xv = *(const float4*)(xpa + k4 * 4);
        xv.x = fmaxf(xv.x, 0.f) * inv;
        xv.y = fmaxf(xv.y, 0.f) * inv;
        xv.z = fmaxf(xv.z, 0.f) * inv;
        xv.w = fmaxf(xv.w, 0.f) * inv;
        int k = k4 * 4;
        fmarow1(acc, pk2(xv.x), ws + (k + 0) * FF);
        fmarow1(acc, pk2(xv.y), ws + (k + 1) * FF);
        fmarow1(acc, pk2(xv.z), ws + (k + 2) * FF);
        fmarow1(acc, pk2(xv.w), ws + (k + 3) * FF);
    }
    if (KP == 64) {
        const float* xpb = accb + (size_t)n * FF;
#pragma unroll
        for (int k4 = 0; k4 < 8; k4++) {
            float4 xv = *(const float4*)(xpb + k4 * 4);
            xv.x = fmaxf(xv.x, 0.f) * inv;
            xv.y = fmaxf(xv.y, 0.f) * inv;
            xv.z = fmaxf(xv.z, 0.f) * inv;
            xv.w = fmaxf(xv.w, 0.f) * inv;
            int k = 32 + k4 * 4;
            fmarow1(acc, pk2(xv.x), ws + (k + 0) * FF);
            fmarow1(acc, pk2(xv.y), ws + (k + 1) * FF);
            fmarow1(acc, pk2(xv.z), ws + (k + 2) * FF);
            fmarow1(acc, pk2(xv.w), ws + (k + 3) * FF);
        }
    }
    float* up = g_uv + (size_t)n * 64 + isV * 32;
#pragma unroll
    for (int j = 0; j < FF; j += 4) *(float4*)(up + j) = *(float4*)(acc.f + j);
}

// ---------------- conv1 (R11 proven pair) ----------------
__global__ __launch_bounds__(128) void k_conv1(const float* __restrict__ ea,
                                               const int* __restrict__ eidx,
                                               const float* __restrict__ w10,
                                               const float* __restrict__ b10,
                                               const float* __restrict__ w11,
                                               const float* __restrict__ b11) {
    __shared__ __align__(16) float s_w0[4 * FF];
    __shared__ __align__(16) float s_b0[FF];
    __shared__ __align__(16) float s_w1[FF * FF];
    __shared__ __align__(16) float s_b1[FF];
    int tid = threadIdx.x, nt = blockDim.x;
    int p = blockIdx.x * nt + tid;
    bool act = p < HALF_E;
    int e0 = 2 * p, e1 = 2 * p + 1;
    float4 a0, a1;
    int r0 = 0, r1 = 0;
    if (act) {
        a0 = *(const float4*)(ea + (size_t)e0 * 4);
        a1 = *(const float4*)(ea + (size_t)e1 * 4);
        r0 = eidx[e0];
        r1 = eidx[e1];
    }
    cpsh(s_w0, w10, 4 * FF, tid, nt);
    cpsh(s_b0, b10, FF, tid, nt);
    cpsh(s_w1, w11, FF * FF, tid, nt);
    cpsh(s_b1, b11, FF, tid, nt);
    __syncthreads();
    if (!act) return;
    V32 h0, h1;
    ldbias(h0, s_b0);
    ldbias(h1, s_b0);
    fmarow2p(h0, h1, pk2(a0.x), pk2(a1.x), s_w0);
    fmarow2p(h0, h1, pk2(a0.y), pk2(a1.y), s_w0 + FF);
    fmarow2p(h0, h1, pk2(a0.z), pk2(a1.z), s_w0 + 2 * FF);
    fmarow2p(h0, h1, pk2(a0.w), pk2(a1.w), s_w0 + 3 * FF);
    relu32(h0);
    relu32(h1);
    V32 o0, o1;
    layer2p(o0, o1, h0, h1, s_w1, s_b1);
    scatter32(g_acc1 + (size_t)r0 * FF, o0);
    scatter32(g_acc1 + (size_t)r1 * FF, o1);
    atomicAdd(&g_cnt[r0], 1.0f);
    atomicAdd(&g_cnt[r1], 1.0f);
    store_relu2T(g_e1, e0, o0, o1);
}

// ================= MMA tile edge kernel (fragment-fed) =================
// MODE 0: edge2 (K1P=40: rows 0-3 ea, 4-35 e1, rest zero)
// MODE 1: edge3 (K1P=64: 0-31 srcA=e2, 32-63 srcB=e1)
// MODE 2: edge4 (K1P=64: 0-31 srcA=e3, 32-63 srcB=e2) + folded heads

template <int MODE>
__device__ __forceinline__ float xld(const float* __restrict__ ea,
                                     const float* __restrict__ srcA,
                                     const float* __restrict__ srcB, int base, int k, int e) {
    if (MODE == 0) {
        if (k < 4) return ea[(size_t)(base + e) * 4 + k];
        if (k < 36) return srcA[(size_t)(k - 4) * EE + base + e];
        return 0.f;
    } else {
        if (k < 32) return srcA[(size_t)k * EE + base + e];
        return srcB[(size_t)(k - 32) * EE + base + e];
    }
}

template <int K1P, int MODE>
__global__ __launch_bounds__(TT) void k_edget(
    const int* __restrict__ eidx, const float* __restrict__ ea,
    const float* __restrict__ srcA, const float* __restrict__ srcB,
    const float* __restrict__ wf1g, const float* __restrict__ wf2g,
    const float* __restrict__ b1src, float* __restrict__ accout, float* __restrict__ eout,
    float* __restrict__ out) {
    extern __shared__ float sm[];
    constexpr int NKB1 = K1P / 8;
    const int WF1 = 0;                      // NKB1*512
    const int WF2 = WF1 + NKB1 * 512;       // 2048
    const int UVB = WF2 + 2048;             // 128*33 = 4224 (reused as Os)
    const int HS = UVB + 4224;              // 32*132 = 4224
    const int B1 = HS + 4224;               // 32
    const int RIDX = B1 + 32;               // 128
    const int HWX = RIDX + 128;             // 128
    const int HWZ = HWX + 128;              // 32
    const int HBX = HWZ + 32;               // 4
    const int HBZ = HBX + 4;                // 1

    float* sWf1 = sm + WF1;
    float* sWf2 = sm + WF2;
    float* uvb = sm + UVB;
    float* Hs = sm + HS;
    float* b1s = sm + B1;
    int* ridx = (int*)(sm + RIDX);
    float* Os = sm + UVB;

    int tid = threadIdx.x;
    int base = blockIdx.x * ET;

    cpsh(sWf1, wf1g, NKB1 * 512, tid, TT);
    cpsh(sWf2, wf2g, 2048, tid, TT);
    if (tid < 32) b1s[tid] = b1src[tid];
    if (MODE == 2) {
        for (int i = tid; i < 128; i += TT) sm[HWX + i] = g_wx[i];
        if (tid < 32) sm[HWZ + tid] = g_wz[tid];
        if (tid < 4) sm[HBX + tid] = g_bx[tid];
        if (tid == 0) sm[HBZ] = g_bz;
    }
    // UV gather (+bias-folded U); ridx
    if (tid < ET) {
        int e = tid;
        int r = eidx[base + e], c = eidx[EE + base + e];
        ridx[e] = r;
        const float4* U = (const float4*)(g_uv + (size_t)r * 64);
        const float4* V = (const float4*)(g_uv + (size_t)c * 64 + 32);
        float* d = uvb + e * 33;
#pragma unroll
        for (int j = 0; j < 8; j++) {
            float4 u = U[j], v = V[j];
            d[4 * j + 0] = u.x + v.x;
            d[4 * j + 1] = u.y + v.y;
            d[4 * j + 2] = u.z + v.z;
            d[4 * j + 3] = u.w + v.w;
        }
    }
    __syncthreads();

    int warp = tid >> 5, lane = tid & 31;
    int g = lane >> 2, tg = lane & 3;
    int m0 = warp * 16;

    // ---- GEMM1: D = UV + X @ W ----
    float acc[4][4];
#pragma unroll
    for (int nb = 0; nb < 4; nb++) {
        int n0 = nb * 8;
        acc[nb][0] = uvb[(m0 + g) * 33 + n0 + 2 * tg];
        acc[nb][1] = uvb[(m0 + g) * 33 + n0 + 2 * tg + 1];
        acc[nb][2] = uvb[(m0 + g + 8) * 33 + n0 + 2 * tg];
        acc[nb][3] = uvb[(m0 + g + 8) * 33 + n0 + 2 * tg + 1];
    }
#pragma unroll
    for (int kb = 0; kb < NKB1; kb++) {
        int k = kb * 8;
        float x0 = xld<MODE>(ea, srcA, srcB, base, k + tg, m0 + g);
        float x1 = xld<MODE>(ea, srcA, srcB, base, k + tg, m0 + g + 8);
        float x2 = xld<MODE>(ea, srcA, srcB, base, k + tg + 4, m0 + g);
        float x3 = xld<MODE>(ea, srcA, srcB, base, k + tg + 4, m0 + g + 8);
        uint a0h, a0l, a1h, a1l, a2h, a2l, a3h, a3l;
        tf32split(x0, a0h, a0l);
        tf32split(x1, a1h, a1l);
        tf32split(x2, a2h, a2l);
        tf32split(x3, a3h, a3l);
#pragma unroll
        for (int nb = 0; nb < 4; nb++) {
            float4 wf = *(const float4*)(sWf1 + ((kb * 4 + nb) * 32 + lane) * 4);
            uint b0h = __float_as_uint(wf.x), b1h = __float_as_uint(wf.y);
            uint b0l = __float_as_uint(wf.z), b1l = __float_as_uint(wf.w);
            mma8(acc[nb][0], acc[nb][1], acc[nb][2], acc[nb][3], a0h, a1h, a2h, a3h, b0h,
                 b1h);
            mma8(acc[nb][0], acc[nb][1], acc[nb][2], acc[nb][3], a0h, a1h, a2h, a3h, b0l,
                 b1l);
            mma8(acc[nb][0], acc[nb][1], acc[nb][2], acc[nb][3], a0l, a1l, a2l, a3l, b0h,
                 b1h);
        }
    }
    // relu(D) -> Hs [n][132] (each warp writes its own 16 columns)
#pragma unroll
    for (int nb = 0; nb < 4; nb++) {
        int n0 = nb * 8;
        Hs[(n0 + 2 * tg) * 132 + m0 + g] = fmaxf(acc[nb][0], 0.f);
        Hs[(n0 + 2 * tg + 1) * 132 + m0 + g] = fmaxf(acc[nb][1], 0.f);
        Hs[(n0 + 2 * tg) * 132 + m0 + g + 8] = fmaxf(acc[nb][2], 0.f);
        Hs[(n0 + 2 * tg + 1) * 132 + m0 + g + 8] = fmaxf(acc[nb][3], 0.f);
    }
    __syncwarp();

    // ---- GEMM2: O = b1 + H @ W1 ----
#pragma unroll
    for (int nb = 0; nb < 4; nb++) {
        int n0 = nb * 8;
        float bA = b1s[n0 + 2 * tg], bB = b1s[n0 + 2 * tg + 1];
        acc[nb][0] = bA;
        acc[nb][1] = bB;
        acc[nb][2] = bA;
        acc[nb][3] = bB;
    }
#pragma unroll
    for (int kb = 0; kb < 4; kb++) {
        int k0 = kb * 8;
        float x0 = Hs[(k0 + tg) * 132 + m0 + g];
        float x1 = Hs[(k0 + tg) * 132 + m0 + g + 8];
        float x2 = Hs[(k0 + tg + 4) * 132 + m0 + g];
        float x3 = Hs[(k0 + tg + 4) * 132 + m0 + g + 8];
        uint a0h, a0l, a1h, a1l, a2h, a2l, a3h, a3l;
        tf32split(x0, a0h, a0l);
        tf32split(x1, a1h, a1l);
        tf32split(x2, a2h, a2l);
        tf32split(x3, a3h, a3l);
#pragma unroll
        for (int nb = 0; nb < 4; nb++) {
            float4 wf = *(const float4*)(sWf2 + ((kb * 4 + nb) * 32 + lane) * 4);
            uint b0h = __float_as_uint(wf.x), b1h = __float_as_uint(wf.y);
            uint b0l = __float_as_uint(wf.z), b1l = __float_as_uint(wf.w);
            mma8(acc[nb][0], acc[nb][1], acc[nb][2], acc[nb][3], a0h, a1h, a2h, a3h, b0h,
                 b1h);
            mma8(acc[nb][0], acc[nb][1], acc[nb][2], acc[nb][3], a0h, a1h, a2h, a3h, b0l,
                 b1l);
            mma8(acc[nb][0], acc[nb][1], acc[nb][2], acc[nb][3], a0l, a1l, a2l, a3l, b0h,
                 b1h);
        }
    }
    // O -> Os [e][33] (each warp writes only its own 16 edge-rows; UV reads done)
#pragma unroll
    for (int nb = 0; nb < 4; nb++) {
        int n0 = nb * 8;
        Os[(m0 + g) * 33 + n0 + 2 * tg] = acc[nb][0];
        Os[(m0 + g) * 33 + n0 + 2 * tg + 1] = acc[nb][1];
        Os[(m0 + g + 8) * 33 + n0 + 2 * tg] = acc[nb][2];
        Os[(m0 + g + 8) * 33 + n0 + 2 * tg + 1] = acc[nb][3];
    }
    __syncthreads();

    // ---- finalize ----
    if (MODE != 2) {
        for (int i = tid; i < 32 * ET; i += TT) {
            int n = i >> 7, e = i & 127;
            eout[(size_t)n * EE + base + e] = fmaxf(Os[e * 33 + n], 0.f);
        }
        int e = tid & 127, half = tid >> 7;
        int r = ridx[e];
        float* ap = accout + (size_t)r * FF + half * 16;
        const float* op = Os + e * 33 + half * 16;
#pragma unroll
        for (int j = 0; j < 4; j++)
            red4(ap + j * 4, op[j * 4 + 0], op[j * 4 + 1], op[j * 4 + 2], op[j * 4 + 3]);
    } else {
        if (tid < ET) {
            int e = tid;
            int edge = base + e;
            float4 a = *(const float4*)(ea + (size_t)edge * 4);
            float x0 = sm[HBX + 0] + a.x, x1 = sm[HBX + 1] + a.y;
            float x2 = sm[HBX + 2] + a.z, x3 = sm[HBX + 3] + a.w;
            float z = sm[HBZ];
#pragma unroll
            for (int k = 0; k < FF; k++) {
                float v = fmaxf(Os[e * 33 + k], 0.f);
                float4 w = *(const float4*)(sm + HWX + k * 4);
                x0 += v * w.x;
                x1 += v * w.y;
                x2 += v * w.z;
                x3 += v * w.w;
                z += v * sm[HWZ + k];
            }
            float nrm = sqrtf(x0 * x0 + x1 * x1 + x2 * x2 + x3 * x3);
            float inv = 1.0f / fmaxf(nrm, 1e-12f);
            *(float4*)(out + (size_t)EE + (size_t)edge * 4) =
                make_float4(x0 * inv, x1 * inv, x2 * inv, x3 * inv);
            out[edge] = 1.0f / (1.0f + expf(-z));
        }
    }
}

#define ETOT(K1P) ((K1P / 8) * 512 + 2048 + 4224 + 4224 + 32 + 128 + 128 + 32 + 4 + 8)

// ---------------- launch ----------------
extern "C" void kernel_launch(void* const* d_in, const int* in_sizes, int n_in,
                              void* d_out, int out_size) {
    const int* eidx = (const int*)d_in[1];
    const float* ea = (const float*)d_in[2];
    const float* beta = (const float*)d_in[3];
    const float* w10 = (const float*)d_in[4];
    const float* b10 = (const float*)d_in[5];
    const float* w11 = (const float*)d_in[6];
    const float* b11 = (const float*)d_in[7];
    const float* w20 = (const float*)d_in[8];
    const float* b20 = (const float*)d_in[9];
    const float* w21 = (const float*)d_in[10];
    const float* b21 = (const float*)d_in[11];
    const float* w30 = (const float*)d_in[12];
    const float* b30 = (const float*)d_in[13];
    const float* w31 = (const float*)d_in[14];
    const float* b31 = (const float*)d_in[15];
    const float* w40 = (const float*)d_in[16];
    const float* b40 = (const float*)d_in[17];
    const float* w41 = (const float*)d_in[18];
    const float* b41 = (const float*)d_in[19];
    const float* wl01 = (const float*)d_in[20];
    const float* bl01 = (const float*)d_in[21];
    const float* wl02 = (const float*)d_in[22];
    const float* bl02 = (const float*)d_in[23];
    const float* wl1 = (const float*)d_in[24];
    const float* bl1 = (const float*)d_in[25];
    const float* wl2 = (const float*)d_in[26];
    const float* bl2 = (const float*)d_in[27];
    float* out = (float*)d_out;

    float *acc1p, *acc2p, *acc3p, *e1p, *e2p, *e3p;
    float *wf20p, *wf30p, *wf40p, *wf21p, *wf31p, *wf41p;
    cudaGetSymbolAddress((void**)&acc1p, g_acc1);
    cudaGetSymbolAddress((void**)&acc2p, g_acc2);
    cudaGetSymbolAddress((void**)&acc3p, g_acc3);
    cudaGetSymbolAddress((void**)&e1p, g_e1);
    cudaGetSymbolAddress((void**)&e2p, g_e2);
    cudaGetSymbolAddress((void**)&e3p, g_e3);
    cudaGetSymbolAddress((void**)&wf20p, g_wf20);
    cudaGetSymbolAddress((void**)&wf30p, g_wf30);
    cudaGetSymbolAddress((void**)&wf40p, g_wf40);
    cudaGetSymbolAddress((void**)&wf21p, g_wf21);
    cudaGetSymbolAddress((void**)&wf31p, g_wf31);
    cudaGetSymbolAddress((void**)&wf41p, g_wf41);

    static int attr_done = 0;
    if (!attr_done) {
        cudaFuncSetAttribute(k_edget<40, 0>, cudaFuncAttributeMaxDynamicSharedMemorySize,
                             ETOT(40) * 4);
        cudaFuncSetAttribute(k_edget<64, 1>, cudaFuncAttributeMaxDynamicSharedMemorySize,
                             ETOT(64) * 4);
        cudaFuncSetAttribute(k_edget<64, 2>, cudaFuncAttributeMaxDynamicSharedMemorySize,
                             ETOT(64) * 4);
        attr_done = 1;
    }

    const int T = 256;
    const int gridNF = (NN * FF + T - 1) / T;
    const int TB = 128;
    const int gridP = (HALF_E + TB - 1) / TB;
    const int gridN = (NN + 127) / 128;

    k_init<<<gridNF, T>>>(beta, out);
    k_headfold<<<1, 192>>>(wl01, bl01, wl02, bl02, wl1, bl1, wl2, bl2);
    k_wpack<<<4, 256>>>(w20, w21, w30, w31, w40, w41);
    k_conv1<<<gridP, TB>>>(ea, eidx, w10, b10, w11, b11);

    k_node<32><<<gridN, 256>>>(acc1p, nullptr, w20, b20);
    k_edget<40, 0><<<NTILE, TT, ETOT(40) * 4>>>(eidx, ea, e1p, nullptr, wf20p, wf21p, b21,
                                                acc2p, e2p, out);

    k_node<64><<<gridN, 256>>>(acc2p, acc1p, w30, b30);
    k_edget<64, 1><<<NTILE, TT, ETOT(64) * 4>>>(eidx, ea, e2p, e1p, wf30p, wf31p, b31,
                                                acc3p, e3p, out);

    k_node<64><<<gridN, 256>>>(acc3p, acc2p, w40, b40);
    k_edget<64, 2><<<NTILE, TT, ETOT(64) * 4>>>(eidx, ea, e3p, e2p, wf40p, wf41p, b41,
                                                nullptr, nullptr, out);
}

// round 16
// speedup vs baseline: 1.7398x; 1.3122x over previous
#include <cuda_runtime.h>
#include <math.h>

#define NN 50000
#define EE 400000
#define FF 32
#define HALF_E (EE / 2)

typedef unsigned long long ull;

// ---------------- scratch ----------------
// e-feature buffers TRANSPOSED: [FF][EE], element (k, e) at k*EE + e
__device__ __align__(128) float g_e1[(size_t)EE * FF];
__device__ __align__(128) float g_e2[(size_t)EE * FF];
__device__ __align__(128) float g_e3[(size_t)EE * FF];
__device__ __align__(128) float g_acc1[(size_t)NN * FF];
__device__ __align__(128) float g_acc2[(size_t)NN * FF];
__device__ __align__(128) float g_acc3[(size_t)NN * FF];
__device__ __align__(128) float g_uv[(size_t)NN * 64];
__device__ __align__(128) float g_cnt[NN];
__device__ __align__(16) float g_wx[FF * 4];
__device__ __align__(16) float g_bx[4];
__device__ __align__(16) float g_wz[FF];
__device__ float g_bz;

// ---------------- f32x2 helpers ----------------
__device__ __forceinline__ void ffma2(ull& d, ull a, ull b) {
    asm("fma.rn.f32x2 %0, %1, %2, %0;" : "+l"(d) : "l"(a), "l"(b));
}
__device__ __forceinline__ ull pk2(float v) {
    ull r;
    asm("mov.b64 %0, {%1, %1};" : "=l"(r) : "f"(v));
    return r;
}
union V32 {
    float f[FF];
    ull u[FF / 2];
};

__device__ __forceinline__ void cpsh(float* dst, const float* src, int n, int tid, int nt) {
    for (int i = tid; i < n; i += nt) dst[i] = src[i];
}
__device__ __forceinline__ void ldbias(V32& h, const float* __restrict__ b) {
#pragma unroll
    for (int j = 0; j < FF; j++) h.f[j] = b[j];
}
__device__ __forceinline__ void relu32(V32& h) {
#pragma unroll
    for (int j = 0; j < FF; j++) h.f[j] = fmaxf(h.f[j], 0.f);
}
__device__ __forceinline__ void red4(float* __restrict__ a, float x, float y, float z, float w) {
    asm volatile("red.global.add.v4.f32 [%0], {%1, %2, %3, %4};" ::"l"(a), "f"(x), "f"(y),
                 "f"(z), "f"(w)
                 : "memory");
}
__device__ __forceinline__ void scatter32(float* __restrict__ acc, const V32& o) {
#pragma unroll
    for (int j = 0; j < FF; j += 4) red4(acc + j, o.f[j], o.f[j + 1], o.f[j + 2], o.f[j + 3]);
}

__device__ __forceinline__ void fmarow1(V32& h, ull v, const float* __restrict__ wr) {
#pragma unroll
    for (int j = 0; j < 8; j++) {
        ulonglong2 w = *(const ulonglong2*)(wr + j * 4);
        ffma2(h.u[2 * j + 0], v, w.x);
        ffma2(h.u[2 * j + 1], v, w.y);
    }
}
__device__ __forceinline__ void fmarow2p(V32& h0, V32& h1, ull v0, ull v1,
                                         const float* __restrict__ wr) {
#pragma unroll
    for (int j = 0; j < 8; j++) {
        ulonglong2 w = *(const ulonglong2*)(wr + j * 4);
        ffma2(h0.u[2 * j + 0], v0, w.x);
        ffma2(h0.u[2 * j + 1], v0, w.y);
        ffma2(h1.u[2 * j + 0], v1, w.x);
        ffma2(h1.u[2 * j + 1], v1, w.y);
    }
}
// transposed-feature segment: gT is [32][EE]; loads (v_e0, v_e1) as float2 per k
__device__ __forceinline__ void seg32pT(V32& h0, V32& h1, const float* __restrict__ gT,
                                        int e0, const float* __restrict__ ws) {
    const float* p = gT + e0;
#pragma unroll
    for (int k = 0; k < FF; k++) {
        float2 v = *(const float2*)(p + (size_t)k * EE);
        fmarow2p(h0, h1, pk2(v.x), pk2(v.y), ws + k * FF);
    }
}
__device__ __forceinline__ void layer2p(V32& o0, V32& o1, const V32& h0, const V32& h1,
                                        const float* __restrict__ sw1,
                                        const float* __restrict__ sb1) {
    ldbias(o0, sb1);
    ldbias(o1, sb1);
#pragma unroll
    for (int k = 0; k < FF; k++) fmarow2p(o0, o1, pk2(h0.f[k]), pk2(h1.f[k]), sw1 + k * FF);
}
__device__ __forceinline__ void store_relu2T(float* __restrict__ gT, int e0, const V32& o0,
                                             const V32& o1) {
    float* p = gT + e0;
#pragma unroll
    for (int j = 0; j < FF; j++) {
        float2 t = make_float2(fmaxf(o0.f[j], 0.f), fmaxf(o1.f[j], 0.f));
        *(float2*)(p + (size_t)j * EE) = t;
    }
}
__device__ __forceinline__ void uvinit(V32& h, int r, int c) {
    const float* U = g_uv + (size_t)r * 64;
    const float* V = g_uv + (size_t)c * 64 + 32;
#pragma unroll
    for (int j = 0; j < FF; j += 4) {
        float4 a = *(const float4*)(U + j);
        float4 b = *(const float4*)(V + j);
        h.f[j + 0] = a.x + b.x;
        h.f[j + 1] = a.y + b.y;
        h.f[j + 2] = a.z + b.z;
        h.f[j + 3] = a.w + b.w;
    }
}

// ---------------- init (vectorized) + head fold fused ----------------
__global__ void k_init(const float* __restrict__ beta, float* __restrict__ out,
                       const float* __restrict__ wl01, const float* __restrict__ bl01,
                       const float* __restrict__ wl02, const float* __restrict__ bl02,
                       const float* __restrict__ wl1, const float* __restrict__ bl1,
                       const float* __restrict__ wl2, const float* __restrict__ bl2) {
    int i = blockIdx.x * blockDim.x + threadIdx.x;
    const int NQ = NN * FF / 4;  // 400000
    float4 z = make_float4(0.f, 0.f, 0.f, 0.f);
    if (i < NQ) {
        ((float4*)g_acc1)[i] = z;
        ((float4*)g_acc2)[i] = z;
        ((float4*)g_acc3)[i] = z;
    }
    if (i < NN) g_cnt[i] = 0.f;
    if (i < 3 * NN) out[(size_t)5 * EE + i] = beta[i];

    // head fold (block 0 only)
    if (blockIdx.x == 0) {
        int t = threadIdx.x;
        if (t < 128) {
            int k = t >> 2, j = t & 3;
            float s = 0.f;
#pragma unroll
            for (int m = 0; m < FF; m++) s += wl01[k * FF + m] * wl1[m * 4 + j];
            g_wx[k * 4 + j] = s;
        }
        if (t < 4) {
            float s = bl1[t];
#pragma unroll
            for (int m = 0; m < FF; m++) s += bl01[m] * wl1[m * 4 + t];
            g_bx[t] = s;
        }
        if (t >= 128 && t < 160) {
            int k = t - 128;
            float s = 0.f;
#pragma unroll
            for (int m = 0; m < FF; m++) s += wl02[k * FF + m] * wl2[m];
            g_wz[k] = s;
        }
        if (t == 160) {
            float s = bl2[0];
#pragma unroll
            for (int m = 0; m < FF; m++) s += bl02[m] * wl2[m];
            g_bz = s;
        }
    }
}

// ---------------- node projection (2-way U/V split, fused finalize) ----------------
template <int KP>
__global__ __launch_bounds__(256) void k_node(const float* __restrict__ acca,
                                              const float* __restrict__ accb,
                                              const float* __restrict__ W0,
                                              const float* __restrict__ b0) {
    __shared__ __align__(16) float s_w[2 * KP * FF];
    __shared__ __align__(16) float s_b[FF];
    int tid = threadIdx.x;

    int n = blockIdx.x * 128 + (tid & 127);
    float cnt = (n < NN) ? g_cnt[n] : 1.0f;

    cpsh(s_w, W0, 2 * KP * FF, tid, 256);
    cpsh(s_b, b0, FF, tid, 256);
    __syncthreads();

    int isV = tid >> 7;
    if (n >= NN) return;

    float inv = 1.0f / fmaxf(cnt, 1.0f);
    const float* ws = s_w + (isV ? KP * FF : 0);

    V32 acc;
    if (isV) {
#pragma unroll
        for (int j = 0; j < FF; j++) acc.f[j] = 0.f;
    } else {
        ldbias(acc, s_b);
    }

    const float* xpa = acca + (size_t)n * FF;
#pragma unroll
    for (int k4 = 0; k4 < 8; k4++) {
        float4 xv = *(const float4*)(xpa + k4 * 4);
        xv.x = fmaxf(xv.x, 0.f) * inv;
        xv.y = fmaxf(xv.y, 0.f) * inv;
        xv.z = fmaxf(xv.z, 0.f) * inv;
        xv.w = fmaxf(xv.w, 0.f) * inv;
        int k = k4 * 4;
        fmarow1(acc, pk2(xv.x), ws + (k + 0) * FF);
        fmarow1(acc, pk2(xv.y), ws + (k + 1) * FF);
        fmarow1(acc, pk2(xv.z), ws + (k + 2) * FF);
        fmarow1(acc, pk2(xv.w), ws + (k + 3) * FF);
    }
    if (KP == 64) {
        const float* xpb = accb + (size_t)n * FF;
#pragma unroll
        for (int k4 = 0; k4 < 8; k4++) {
            float4 xv = *(const float4*)(xpb + k4 * 4);
            xv.x = fmaxf(xv.x, 0.f) * inv;
            xv.y = fmaxf(xv.y, 0.f) * inv;
            xv.z = fmaxf(xv.z, 0.f) * inv;
            xv.w = fmaxf(xv.w, 0.f) * inv;
            int k = 32 + k4 * 4;
            fmarow1(acc, pk2(xv.x), ws + (k + 0) * FF);
            fmarow1(acc, pk2(xv.y), ws + (k + 1) * FF);
            fmarow1(acc, pk2(xv.z), ws + (k + 2) * FF);
            fmarow1(acc, pk2(xv.w), ws + (k + 3) * FF);
        }
    }

    float* up = g_uv + (size_t)n * 64 + isV * 32;
#pragma unroll
    for (int j = 0; j < FF; j += 4) *(float4*)(up + j) = *(float4*)(acc.f + j);
}

// ---------------- conv1 (pair; prefetch before barrier; transposed e1 store) ----------------
__global__ __launch_bounds__(128) void k_conv1(const float* __restrict__ ea,
                                               const int* __restrict__ eidx,
                                               const float* __restrict__ w10,
                                               const float* __restrict__ b10,
                                               const float* __restrict__ w11,
                                               const float* __restrict__ b11) {
    __shared__ __align__(16) float s_w0[4 * FF];
    __shared__ __align__(16) float s_b0[FF];
    __shared__ __align__(16) float s_w1[FF * FF];
    __shared__ __align__(16) float s_b1[FF];
    int tid = threadIdx.x, nt = blockDim.x;

    int p = blockIdx.x * nt + tid;
    bool act = p < HALF_E;
    int e0 = 2 * p, e1 = 2 * p + 1;
    float4 a0, a1;
    int r0 = 0, r1 = 0;
    if (act) {
        a0 = *(const float4*)(ea + (size_t)e0 * 4);
        a1 = *(const float4*)(ea + (size_t)e1 * 4);
        r0 = eidx[e0];
        r1 = eidx[e1];
    }

    cpsh(s_w0, w10, 4 * FF, tid, nt);
    cpsh(s_b0, b10, FF, tid, nt);
    cpsh(s_w1, w11, FF * FF, tid, nt);
    cpsh(s_b1, b11, FF, tid, nt);
    __syncthreads();
    if (!act) return;

    V32 h0, h1;
    ldbias(h0, s_b0);
    ldbias(h1, s_b0);
    fmarow2p(h0, h1, pk2(a0.x), pk2(a1.x), s_w0);
    fmarow2p(h0, h1, pk2(a0.y), pk2(a1.y), s_w0 + FF);
    fmarow2p(h0, h1, pk2(a0.z), pk2(a1.z), s_w0 + 2 * FF);
    fmarow2p(h0, h1, pk2(a0.w), pk2(a1.w), s_w0 + 3 * FF);
    relu32(h0);
    relu32(h1);

    V32 o0, o1;
    layer2p(o0, o1, h0, h1, s_w1, s_b1);

    scatter32(g_acc1 + (size_t)r0 * FF, o0);
    scatter32(g_acc1 + (size_t)r1 * FF, o1);
    atomicAdd(&g_cnt[r0], 1.0f);
    atomicAdd(&g_cnt[r1], 1.0f);
    store_relu2T(g_e1, e0, o0, o1);
}

// ---------------- edge2 ----------------
__global__ __launch_bounds__(128) void k_edge2(const float* __restrict__ ea,
                                               const int* __restrict__ eidx,
                                               const float* __restrict__ w20,
                                               const float* __restrict__ w21,
                                               const float* __restrict__ b21) {
    __shared__ __align__(16) float s_w0e[36 * FF];
    __shared__ __align__(16) float s_w1[FF * FF];
    __shared__ __align__(16) float s_b1[FF];
    int tid = threadIdx.x, nt = blockDim.x;

    int p = blockIdx.x * nt + tid;
    bool act = p < HALF_E;
    int e0 = 2 * p, e1 = 2 * p + 1;
    int r0 = 0, c0 = 0, r1 = 0, c1 = 0;
    float4 a0, a1;
    V32 h0, h1;
    if (act) {
        r0 = eidx[e0];
        c0 = eidx[EE + e0];
        r1 = eidx[e1];
        c1 = eidx[EE + e1];
        uvinit(h0, r0, c0);
        uvinit(h1, r1, c1);
        a0 = *(const float4*)(ea + (size_t)e0 * 4);
        a1 = *(const float4*)(ea + (size_t)e1 * 4);
    }

    cpsh(s_w0e, w20 + 64 * FF, 36 * FF, tid, nt);
    cpsh(s_w1, w21, FF * FF, tid, nt);
    cpsh(s_b1, b21, FF, tid, nt);
    __syncthreads();
    if (!act) return;

    fmarow2p(h0, h1, pk2(a0.x), pk2(a1.x), s_w0e);
    fmarow2p(h0, h1, pk2(a0.y), pk2(a1.y), s_w0e + FF);
    fmarow2p(h0, h1, pk2(a0.z), pk2(a1.z), s_w0e + 2 * FF);
    fmarow2p(h0, h1, pk2(a0.w), pk2(a1.w), s_w0e + 3 * FF);
    seg32pT(h0, h1, g_e1, e0, s_w0e + 4 * FF);
    relu32(h0);
    relu32(h1);

    V32 o0, o1;
    layer2p(o0, o1, h0, h1, s_w1, s_b1);

    scatter32(g_acc2 + (size_t)r0 * FF, o0);
    scatter32(g_acc2 + (size_t)r1 * FF, o1);
    store_relu2T(g_e2, e0, o0, o1);
}

// ---------------- edge3 ----------------
__global__ __launch_bounds__(128) void k_edge3(const int* __restrict__ eidx,
                                               const float* __restrict__ w30,
                                               const float* __restrict__ w31,
                                               const float* __restrict__ b31) {
    __shared__ __align__(16) float s_w0e[64 * FF];
    __shared__ __align__(16) float s_w1[FF * FF];
    __shared__ __align__(16) float s_b1[FF];
    int tid = threadIdx.x, nt = blockDim.x;

    int p = blockIdx.x * nt + tid;
    bool act = p < HALF_E;
    int e0 = 2 * p, e1 = 2 * p + 1;
    int r0 = 0, c0 = 0, r1 = 0, c1 = 0;
    V32 h0, h1;
    if (act) {
        r0 = eidx[e0];
        c0 = eidx[EE + e0];
        r1 = eidx[e1];
        c1 = eidx[EE + e1];
        uvinit(h0, r0, c0);
        uvinit(h1, r1, c1);
    }

    cpsh(s_w0e, w30 + 128 * FF, 64 * FF, tid, nt);
    cpsh(s_w1, w31, FF * FF, tid, nt);
    cpsh(s_b1, b31, FF, tid, nt);
    __syncthreads();
    if (!act) return;

    seg32pT(h0, h1, g_e2, e0, s_w0e);
    seg32pT(h0, h1, g_e1, e0, s_w0e + 32 * FF);
    relu32(h0);
    relu32(h1);

    V32 o0, o1;
    layer2p(o0, o1, h0, h1, s_w1, s_b1);

    scatter32(g_acc3 + (size_t)r0 * FF, o0);
    scatter32(g_acc3 + (size_t)r1 * FF, o1);
    store_relu2T(g_e3, e0, o0, o1);
}

// ---------------- edge4 + folded heads ----------------
__global__ __launch_bounds__(128) void k_edge4(const float* __restrict__ ea,
                                               const int* __restrict__ eidx,
                                               const float* __restrict__ w40,
                                               const float* __restrict__ w41,
                                               const float* __restrict__ b41,
                                               float* __restrict__ out) {
    __shared__ __align__(16) float s_w0e[64 * FF];
    __shared__ __align__(16) float s_w1[FF * FF];
    __shared__ __align__(16) float s_b1[FF];
    __shared__ __align__(16) float s_wx[FF * 4];
    __shared__ __align__(16) float s_wz[FF];
    __shared__ float s_bx[4];
    __shared__ float s_bz;
    int tid = threadIdx.x, nt = blockDim.x;

    int p = blockIdx.x * nt + tid;
    bool act = p < HALF_E;
    int e0 = 2 * p, e1 = 2 * p + 1;
    int r0 = 0, c0 = 0, r1 = 0, c1 = 0;
    float4 a0, a1;
    V32 h0, h1;
    if (act) {
        r0 = eidx[e0];
        c0 = eidx[EE + e0];
        r1 = eidx[e1];
        c1 = eidx[EE + e1];
        uvinit(h0, r0, c0);
        uvinit(h1, r1, c1);
        a0 = *(const float4*)(ea + (size_t)e0 * 4);
        a1 = *(const float4*)(ea + (size_t)e1 * 4);
    }

    cpsh(s_w0e, w40 + 128 * FF, 64 * FF, tid, nt);
    cpsh(s_w1, w41, FF * FF, tid, nt);
    cpsh(s_b1, b41, FF, tid, nt);
    cpsh(s_wx, g_wx, FF * 4, tid, nt);
    cpsh(s_wz, g_wz, FF, tid, nt);
    if (tid < 4) s_bx[tid] = g_bx[tid];
    if (tid == 0) s_bz = g_bz;
    __syncthreads();
    if (!act) return;

    seg32pT(h0, h1, g_e3, e0, s_w0e);
    seg32pT(h0, h1, g_e2, e0, s_w0e + 32 * FF);
    relu32(h0);
    relu32(h1);

    V32 e40, e41;
    layer2p(e40, e41, h0, h1, s_w1, s_b1);
    relu32(e40);
    relu32(e41);

    float x00 = s_bx[0] + a0.x, x01 = s_bx[1] + a0.y, x02 = s_bx[2] + a0.z,
          x03 = s_bx[3] + a0.w;
    float x10 = s_bx[0] + a1.x, x11 = s_bx[1] + a1.y, x12 = s_bx[2] + a1.z,
          x13 = s_bx[3] + a1.w;
    float z0 = s_bz, z1 = s_bz;
#pragma unroll
    for (int k = 0; k < FF; k++) {
        float4 w = *(const float4*)(s_wx + k * 4);
        float wzk = s_wz[k];
        float v0 = e40.f[k], v1 = e41.f[k];
        x00 += v0 * w.x;
        x01 += v0 * w.y;
        x02 += v0 * w.z;
        x03 += v0 * w.w;
        z0 += v0 * wzk;
        x10 += v1 * w.x;
        x11 += v1 * w.y;
        x12 += v1 * w.z;
        x13 += v1 * w.w;
        z1 += v1 * wzk;
    }
    {
        float nrm = sqrtf(x00 * x00 + x01 * x01 + x02 * x02 + x03 * x03);
        float inv = 1.0f / fmaxf(nrm, 1e-12f);
        *(float4*)(out + (size_t)EE + (size_t)e0 * 4) =
            make_float4(x00 * inv, x01 * inv, x02 * inv, x03 * inv);
    }
    {
        float nrm = sqrtf(x10 * x10 + x11 * x11 + x12 * x12 + x13 * x13);
        float inv = 1.0f / fmaxf(nrm, 1e-12f);
        *(float4*)(out + (size_t)EE + (size_t)e1 * 4) =
            make_float4(x10 * inv, x11 * inv, x12 * inv, x13 * inv);
    }
    out[e0] = 1.0f / (1.0f + expf(-z0));
    out[e1] = 1.0f / (1.0f + expf(-z1));
}

// ---------------- launch ----------------
extern "C" void kernel_launch(void* const* d_in, const int* in_sizes, int n_in,
                              void* d_out, int out_size) {
    const int* eidx = (const int*)d_in[1];
    const float* ea = (const float*)d_in[2];
    const float* beta = (const float*)d_in[3];
    const float* w10 = (const float*)d_in[4];
    const float* b10 = (const float*)d_in[5];
    const float* w11 = (const float*)d_in[6];
    const float* b11 = (const float*)d_in[7];
    const float* w20 = (const float*)d_in[8];
    const float* b20 = (const float*)d_in[9];
    const float* w21 = (const float*)d_in[10];
    const float* b21 = (const float*)d_in[11];
    const float* w30 = (const float*)d_in[12];
    const float* b30 = (const float*)d_in[13];
    const float* w31 = (const float*)d_in[14];
    const float* b31 = (const float*)d_in[15];
    const float* w40 = (const float*)d_in[16];
    const float* b40 = (const float*)d_in[17];
    const float* w41 = (const float*)d_in[18];
    const float* b41 = (const float*)d_in[19];
    const float* wl01 = (const float*)d_in[20];
    const float* bl01 = (const float*)d_in[21];
    const float* wl02 = (const float*)d_in[22];
    const float* bl02 = (const float*)d_in[23];
    const float* wl1 = (const float*)d_in[24];
    const float* bl1 = (const float*)d_in[25];
    const float* wl2 = (const float*)d_in[26];
    const float* bl2 = (const float*)d_in[27];
    float* out = (float*)d_out;

    float *acc1p, *acc2p, *acc3p;
    cudaGetSymbolAddress((void**)&acc1p, g_acc1);
    cudaGetSymbolAddress((void**)&acc2p, g_acc2);
    cudaGetSymbolAddress((void**)&acc3p, g_acc3);

    const int T = 256;
    // init grid: covers NN*FF/4 quad-stores and 3*NN beta copies (400000 > 150000)
    const int gridI = (NN * FF / 4 + T - 1) / T;
    const int TB = 128;
    const int gridP = (HALF_E + TB - 1) / TB;
    const int gridN = (NN + 127) / 128;

    k_init<<<gridI, T>>>(beta, out, wl01, bl01, wl02, bl02, wl1, bl1, wl2, bl2);
    k_conv1<<<gridP, TB>>>(ea, eidx, w10, b10, w11, b11);

    k_node<32><<<gridN, 256>>>(acc1p, nullptr, w20, b20);
    k_edge2<<<gridP, TB>>>(ea, eidx, w20, w21, b21);

    k_node<64><<<gridN, 256>>>(acc2p, acc1p, w30, b30);
    k_edge3<<<gridP, TB>>>(eidx, w30, w31, b31);

    k_node<64><<<gridN, 256>>>(acc3p, acc2p, w40, b40);
    k_edge4<<<gridP, TB>>>(ea, eidx, w40, w41, b41, out);
}